// round 4
// baseline (speedup 1.0000x reference)
#include <cuda_runtime.h>

// Problem shape (fixed by dataset): D=1024, P=256, R=64, K=1024
#define D_DIRS 1024
#define P_PTS  256
#define R_RANK 64
#define K_SUB  1024

// Scratch (allocation-free rule: __device__ global)
__device__ float g_M[R_RANK * R_RANK];  // M[r1][r2] = sum_d asum[d,r1]*bsum[d,r2]

// ---------------------------------------------------------------------------
// Fused streaming kernel: one block per direction d. Each block streams BOTH
// 64 KB slabs (atten[d], rad[d]) with coalesced float4 __ldcs loads (all
// batched up front for max MLP), reduces each over P to a 64-float vector,
// then accumulates the rank-1 outer product asum_d (x) bsum_d into g_M via
// one atomicAdd sweep (4096 adds/block; per-address pipelined at the LTS).
// grid=1024, 256 thr, ~7 blocks/SM -> single-wave full-chip streaming.
// ---------------------------------------------------------------------------
__global__ __launch_bounds__(256) void fused_stream_kernel(
    const float* __restrict__ atten, const float* __restrict__ rad)
{
    const int d = blockIdx.x;
    const int t = threadIdx.x;

    const float4* __restrict__ inA =
        reinterpret_cast<const float4*>(atten) + (size_t)d * 4096;
    const float4* __restrict__ inB =
        reinterpret_cast<const float4*>(rad) + (size_t)d * 4096;

    // ---- batched loads: 16 float4 from each tensor per thread ----
    float4 accA = make_float4(0.f, 0.f, 0.f, 0.f);
    float4 accB = make_float4(0.f, 0.f, 0.f, 0.f);
    #pragma unroll
    for (int i = 0; i < 16; i++) {
        float4 va = __ldcs(&inA[i * 256 + t]);
        float4 vb = __ldcs(&inB[i * 256 + t]);
        accA.x += va.x; accA.y += va.y; accA.z += va.z; accA.w += va.w;
        accB.x += vb.x; accB.y += vb.y; accB.z += vb.z; accB.w += vb.w;
    }

    __shared__ float4 s[256];
    __shared__ float asum[R_RANK];
    __shared__ float bsum[R_RANK];

    // ---- tree-reduce A ----
    s[t] = accA;
    __syncthreads();
    if (t < 16) {
        float4 sum = s[t];
        #pragma unroll
        for (int j = 1; j < 16; j++) {
            float4 v = s[j * 16 + t];
            sum.x += v.x; sum.y += v.y; sum.z += v.z; sum.w += v.w;
        }
        reinterpret_cast<float4*>(asum)[t] = sum;
    }
    __syncthreads();

    // ---- tree-reduce B ----
    s[t] = accB;
    __syncthreads();
    if (t < 16) {
        float4 sum = s[t];
        #pragma unroll
        for (int j = 1; j < 16; j++) {
            float4 v = s[j * 16 + t];
            sum.x += v.x; sum.y += v.y; sum.z += v.z; sum.w += v.w;
        }
        reinterpret_cast<float4*>(bsum)[t] = sum;
    }
    __syncthreads();

    // ---- rank-1 outer product -> atomic accumulate into g_M ----
    // thread t owns r1 = t>>2, r2 in [(t&3)*16, +16)
    const int r1  = t >> 2;
    const int r2b = (t & 3) * 16;
    const float a = asum[r1];
    #pragma unroll
    for (int j = 0; j < 16; j++)
        atomicAdd(&g_M[r1 * R_RANK + r2b + j], a * bsum[r2b + j]);
}

// ---------------------------------------------------------------------------
// Quadform: csi[k] = (1/D) * f_k^T M f_k.
// grid=128 x 256 threads: one warp per k (8 k's per block), lane owns an r2
// float2. M staged once per block in smem (coalesced 16 KB load).
// ---------------------------------------------------------------------------
__global__ __launch_bounds__(256) void quadform_kernel(
    const float* __restrict__ F, float* __restrict__ out)
{
    __shared__ float Msh[R_RANK * R_RANK];   // 16 KB
    __shared__ float fsh[8][R_RANK];         // 2 KB

    const int t    = threadIdx.x;
    const int w    = t >> 5;      // warp = local k
    const int lane = t & 31;
    const int k    = blockIdx.x * 8 + w;

    #pragma unroll
    for (int i = 0; i < 4; i++)
        reinterpret_cast<float4*>(Msh)[i * 256 + t] =
            reinterpret_cast<const float4*>(g_M)[i * 256 + t];

    if (t < 128)
        reinterpret_cast<float4*>(&fsh[0][0])[t] =
            reinterpret_cast<const float4*>(F + (size_t)blockIdx.x * 8 * R_RANK)[t];
    __syncthreads();

    float2 acc = make_float2(0.f, 0.f);
    const float2* __restrict__ M2 = reinterpret_cast<const float2*>(Msh);
    #pragma unroll
    for (int r1 = 0; r1 < R_RANK; r1++) {
        const float fv = fsh[w][r1];          // warp-uniform broadcast
        const float2 m = M2[r1 * 32 + lane];
        acc.x += fv * m.x;
        acc.y += fv * m.y;
    }
    float val = acc.x * fsh[w][2 * lane] + acc.y * fsh[w][2 * lane + 1];

    #pragma unroll
    for (int off = 16; off > 0; off >>= 1)
        val += __shfl_xor_sync(0xffffffffu, val, off);

    if (lane == 0)
        out[k] = val * (1.0f / (float)D_DIRS);
}

extern "C" void kernel_launch(void* const* d_in, const int* in_sizes, int n_in,
                              void* d_out, int out_size)
{
    const float* atten = (const float*)d_in[0];   // [D,P,R] fp32
    const float* rad   = (const float*)d_in[1];   // [D,P,R] fp32
    const float* F     = (const float*)d_in[2];   // [K,R]   fp32
    float* out = (float*)d_out;                   // [K]     fp32

    (void)in_sizes; (void)n_in; (void)out_size;

    // zero the M accumulator (capturable memset node; no allocation)
    void* m_addr = nullptr;
    cudaGetSymbolAddress(&m_addr, g_M);
    cudaMemsetAsync(m_addr, 0, R_RANK * R_RANK * sizeof(float));

    fused_stream_kernel<<<D_DIRS, 256>>>(atten, rad);
    quadform_kernel<<<K_SUB / 8, 256>>>(F, out);
}

// round 5
// speedup vs baseline: 3.1251x; 3.1251x over previous
#include <cuda_runtime.h>

// Problem shape (fixed by dataset): D=1024, P=256, R=64, K=1024
#define D_DIRS 1024
#define P_PTS  256
#define R_RANK 64
#define K_SUB  1024

#define TAIL_BLOCKS 64

// Scratch (allocation-free rule: __device__ globals; zero-initialized at load)
__device__ float g_asum[D_DIRS * R_RANK];              // sum over p of attenuation
__device__ float g_bsum[D_DIRS * R_RANK];              // sum over p of radiation
__device__ float g_part[TAIL_BLOCKS * R_RANK * R_RANK]; // per-block partial M (1 MB)
__device__ float g_M[R_RANK * R_RANK];                 // final M
__device__ unsigned g_c1, g_c2, g_c3;                  // phase counters (reset each run)

// ---------------------------------------------------------------------------
// Kernel 1: reduce over P. One block per (tensor, d) — 2048 short-lived,
// barrier-light blocks; proven 23.8us @ 72% DRAM. Do not restructure.
// ---------------------------------------------------------------------------
__global__ __launch_bounds__(256) void reduce_p_kernel(
    const float* __restrict__ atten, const float* __restrict__ rad)
{
    const int b = blockIdx.x;
    const bool is_b = (b >= D_DIRS);
    const int d = b & (D_DIRS - 1);
    const float* __restrict__ src = is_b ? rad : atten;
    float* __restrict__ dst = is_b ? g_bsum : g_asum;

    const float4* __restrict__ in =
        reinterpret_cast<const float4*>(src) + (size_t)d * (P_PTS * R_RANK / 4);

    const int t = threadIdx.x;

    float4 acc = make_float4(0.f, 0.f, 0.f, 0.f);
    #pragma unroll
    for (int i = 0; i < 16; i++) {
        float4 v = __ldcs(&in[i * 256 + t]);
        acc.x += v.x; acc.y += v.y; acc.z += v.z; acc.w += v.w;
    }

    __shared__ float4 s[256];
    s[t] = acc;
    __syncthreads();

    if (t < 16) {
        float4 sum = s[t];
        #pragma unroll
        for (int j = 1; j < 16; j++) {
            float4 v = s[j * 16 + t];
            sum.x += v.x; sum.y += v.y; sum.z += v.z; sum.w += v.w;
        }
        reinterpret_cast<float4*>(dst + d * R_RANK)[t] = sum;
    }
}

// block-count spin barrier (all TAIL_BLOCKS blocks are co-resident: 64 blocks
// of 256 threads on 152 SMs, so spinning cannot deadlock)
__device__ __forceinline__ void grid_barrier(unsigned* ctr)
{
    __threadfence();
    __syncthreads();
    if (threadIdx.x == 0) {
        atomicAdd(ctr, 1u);
        while (atomicAdd(ctr, 0u) < (unsigned)TAIL_BLOCKS) { }
    }
    __syncthreads();
    __threadfence();
}

// ---------------------------------------------------------------------------
// Kernel 2 (single tail kernel): make_m + combine + quadform, phase-separated
// by spin barriers. grid = 64 blocks x 256 threads.
// ---------------------------------------------------------------------------
__global__ __launch_bounds__(256) void tail_kernel(
    const float* __restrict__ F, float* __restrict__ out)
{
    __shared__ __align__(16) float pool[5120];   // 20 KB, reused across phases
    const int t = threadIdx.x;
    const int b = blockIdx.x;

    // ================= Phase 1: partial M over 16 d's =================
    {
        float* sA = pool;          // [16][64]
        float* sB = pool + 1024;   // [16][64]
        const int dbase = b * 16;

        reinterpret_cast<float4*>(sA)[t] =
            reinterpret_cast<const float4*>(g_asum + dbase * R_RANK)[t];
        reinterpret_cast<float4*>(sB)[t] =
            reinterpret_cast<const float4*>(g_bsum + dbase * R_RANK)[t];
        __syncthreads();

        const int r1  = t >> 2;
        const int r2b = (t & 3) * 16;

        float macc[16];
        #pragma unroll
        for (int j = 0; j < 16; j++) macc[j] = 0.f;

        #pragma unroll
        for (int i = 0; i < 16; i++) {
            const float a = sA[i * R_RANK + r1];
            #pragma unroll
            for (int j = 0; j < 16; j++)
                macc[j] += a * sB[i * R_RANK + r2b + j];
        }

        float* dst = g_part + (size_t)b * 4096 + r1 * R_RANK + r2b;
        #pragma unroll
        for (int j = 0; j < 4; j++)
            reinterpret_cast<float4*>(dst)[j] =
                make_float4(macc[4*j], macc[4*j+1], macc[4*j+2], macc[4*j+3]);
    }

    grid_barrier(&g_c1);

    // ============ Phase 2: combine partials -> M row b ============
    {
        float* s = pool;   // [256]
        const int r2 = t & 63;
        const int g  = t >> 6;     // 4 partial-groups of 16

        float acc = 0.f;
        #pragma unroll
        for (int i = 0; i < 16; i++) {
            const int p = g * 16 + i;
            acc += g_part[(size_t)p * 4096 + b * R_RANK + r2];
        }
        s[t] = acc;
        __syncthreads();
        if (t < 64)
            g_M[b * R_RANK + t] = s[t] + s[64 + t] + s[128 + t] + s[192 + t];
    }

    grid_barrier(&g_c2);

    // ============ Phase 3: quadform for k in [16b, 16b+16) ============
    {
        float* Msh = pool;          // [64][64] = 16 KB
        float* fsh = pool + 4096;   // [16][64] = 4 KB

        #pragma unroll
        for (int i = 0; i < 4; i++)
            reinterpret_cast<float4*>(Msh)[i * 256 + t] =
                reinterpret_cast<const float4*>(g_M)[i * 256 + t];

        reinterpret_cast<float4*>(fsh)[t] =
            reinterpret_cast<const float4*>(F + (size_t)b * 16 * R_RANK)[t];
        __syncthreads();

        const int klocal = t >> 4;   // 0..15
        const int l16    = t & 15;   // owns float4 at r2 = 4*l16
        const float* fk  = fsh + klocal * R_RANK;
        const float4* M4 = reinterpret_cast<const float4*>(Msh);

        float4 acc = make_float4(0.f, 0.f, 0.f, 0.f);
        #pragma unroll
        for (int r1 = 0; r1 < R_RANK; r1++) {
            const float fv = fk[r1];            // broadcast within warp halves
            const float4 m = M4[r1 * 16 + l16];
            acc.x += fv * m.x; acc.y += fv * m.y;
            acc.z += fv * m.z; acc.w += fv * m.w;
        }
        const float4 fq = reinterpret_cast<const float4*>(fk)[l16];
        float val = acc.x * fq.x + acc.y * fq.y + acc.z * fq.z + acc.w * fq.w;

        // reduce 16 lanes (stays within each 16-lane half of the warp)
        #pragma unroll
        for (int off = 8; off > 0; off >>= 1)
            val += __shfl_xor_sync(0xffffffffu, val, off);

        if (l16 == 0)
            out[b * 16 + klocal] = val * (1.0f / (float)D_DIRS);
    }

    // ============ Cleanup: last block resets counters for next replay ====
    __syncthreads();
    if (t == 0) {
        unsigned old = atomicAdd(&g_c3, 1u);
        if (old == (unsigned)(TAIL_BLOCKS - 1)) {
            g_c1 = 0u; g_c2 = 0u; g_c3 = 0u;
        }
    }
}

extern "C" void kernel_launch(void* const* d_in, const int* in_sizes, int n_in,
                              void* d_out, int out_size)
{
    const float* atten = (const float*)d_in[0];   // [D,P,R] fp32
    const float* rad   = (const float*)d_in[1];   // [D,P,R] fp32
    const float* F     = (const float*)d_in[2];   // [K,R]   fp32
    float* out = (float*)d_out;                   // [K]     fp32

    (void)in_sizes; (void)n_in; (void)out_size;

    reduce_p_kernel<<<2 * D_DIRS, 256>>>(atten, rad);
    tail_kernel<<<TAIL_BLOCKS, 256>>>(F, out);
}